// round 5
// baseline (speedup 1.0000x reference)
#include <cuda_runtime.h>
#include <cuda_fp16.h>

#define NN 200000
#define EE 3200000

// ---------------- static device scratch ----------------
__device__ int    g_deg[NN];
__device__ int    g_cnt[NN];
__device__ float  g_dinv[NN];
__device__ int    g_off[NN + 1];
__device__ int    g_cur[NN];
__device__ int    g_bsum[1024];
__device__ int    g_is64;
__device__ int    g_src[EE];
__device__ float4 g_h[NN * 8];     // fp32 feature buffers (float4-aligned)
__device__ float4 g_a[NN * 8];
__device__ float4 g_t[NN * 8];
__device__ float4 g_b[NN * 8];
__device__ uint4  s_h[NN * 4];     // fp16 shadows (pre-scaled by dinv), uint4-aligned
__device__ uint4  s_a[NN * 4];
__device__ uint4  s_t[NN * 4];
__device__ uint4  s_b[NN * 4];

__device__ __forceinline__ float4* fbuf(int id) {
    switch (id) { case 0: return g_h; case 1: return g_a; case 2: return g_t; default: return g_b; }
}
__device__ __forceinline__ uint4* hbuf(int id) {
    switch (id) { case 0: return s_h; case 1: return s_a; case 2: return s_t; default: return s_b; }
}

__device__ __forceinline__ int edge_at(const void* ei, int idx, int is64) {
    if (is64) return (int)((const long long*)ei)[idx];
    return ((const int*)ei)[idx];
}

// ---------------- setup: zero + dtype detect (block 0) ----------------
__global__ void k_dz(const void* ei, int n) {
    int i = blockIdx.x * blockDim.x + threadIdx.x;
    if (i < n) { g_deg[i] = 0; g_cnt[i] = 0; }
    if (blockIdx.x == 0) {
        __shared__ int any;
        if (threadIdx.x == 0) any = 0;
        __syncthreads();
        const int* w = (const int*)ei;
        for (int k = threadIdx.x; k < 1024; k += blockDim.x)
            if (w[2 * k + 1] != 0) atomicOr(&any, 1);
        __syncthreads();
        if (threadIdx.x == 0) g_is64 = (any == 0) ? 1 : 0;
    }
}

__global__ void k_count(const void* ei, int e) {
    int i = blockIdx.x * blockDim.x + threadIdx.x;
    if (i < e) {
        int is64 = g_is64;
        int s = edge_at(ei, i, is64);
        int d = edge_at(ei, e + i, is64);
        atomicAdd(&g_deg[s], 1);
        atomicAdd(&g_cnt[d], 1);
    }
}

// scan part 1 (+ dinv)
__global__ void k_scan1(int n) {
    __shared__ int sh[1024];
    int tid = threadIdx.x;
    int i = blockIdx.x * 1024 + tid;
    if (i < n) {
        int d = g_deg[i];
        g_dinv[i] = (d > 0) ? rsqrtf((float)d) : 0.f;
    }
    int v = (i < n) ? g_cnt[i] : 0;
    sh[tid] = v;
    __syncthreads();
    for (int d = 1; d < 1024; d <<= 1) {
        int t = (tid >= d) ? sh[tid - d] : 0;
        __syncthreads();
        sh[tid] += t;
        __syncthreads();
    }
    if (i < n) g_off[i] = sh[tid] - v;
    if (tid == 1023) g_bsum[blockIdx.x] = sh[1023];
}

// scan parts 2+3 fused: each block computes its bsum prefix (warp-parallel), applies it
__global__ void k_scan23(int n) {
    __shared__ int spfx;
    int tid = threadIdx.x;
    if (tid < 32) {
        int p = 0;
        for (int b = tid; b < (int)blockIdx.x; b += 32) p += g_bsum[b];
#pragma unroll
        for (int o = 16; o > 0; o >>= 1) p += __shfl_xor_sync(0xffffffffu, p, o);
        if (tid == 0) spfx = p;
    }
    __syncthreads();
    int i = blockIdx.x * 1024 + tid;
    if (i < n) {
        int o = g_off[i] + spfx;
        g_off[i] = o;
        g_cur[i] = o;
        if (i == n - 1) g_off[n] = o + g_cnt[i];
    }
}

// ---------------- fused scatter (i < e) + input MLP (i < n*32) ----------------
__global__ void k_scatin(const void* ei, int e, const float* __restrict__ x,
                         const float* __restrict__ W0, const float* __restrict__ b0, int n) {
    __shared__ float sw[96];
    __shared__ float sb[32];
    int tid = threadIdx.x;
    if (tid < 96) sw[tid] = W0[tid];
    if (tid < 32) sb[tid] = b0[tid];
    __syncthreads();
    int i = blockIdx.x * blockDim.x + tid;
    if (i < e) {
        int is64 = g_is64;
        int s = edge_at(ei, i, is64);
        int d = edge_at(ei, e + i, is64);
        int p = atomicAdd(&g_cur[d], 1);
        g_src[p] = s;
    }
    if (i < n * 32) {
        int node = i >> 5, f = i & 31;
        float x0 = x[node * 3 + 0];
        float x1 = x[node * 3 + 1];
        float x2 = x[node * 3 + 2];
        float o = sb[f] + x0 * sw[f] + x1 * sw[32 + f] + x2 * sw[64 + f];
        o = fmaxf(o, 0.f);
        ((float*)g_h)[i] = o;
        float di = g_dinv[node];
        float o_hi = __shfl_down_sync(0xffffffffu, o, 1);
        if ((f & 1) == 0)
            ((__half2*)s_h)[node * 16 + (f >> 1)] = __floats2half2_rn(di * o, di * o_hi);
    }
}

// -------- warp gather core: 8 edges per LDG.128, src indices bulk-preloaded --------
// On return: every lane holds the full row sum for its chunk c = lane&3 in acc[0..7]
// (features c*8 .. c*8+7); lanes with equal c are identical.
__device__ __forceinline__ void gather8(const uint4* __restrict__ rows,
                                        int s, int e, int lane, float acc[8]) {
    int g = lane >> 2, c = lane & 3;
    const unsigned full = 0xffffffffu;
    for (int base = s; base < e; base += 32) {
        int cnt = e - base; if (cnt > 32) cnt = 32;
        int my = (lane < cnt) ? __ldg(&g_src[base + lane]) : 0;
#pragma unroll 4
        for (int it = 0; it < cnt; it += 8) {
            int slot = it + g;
            int src = __shfl_sync(full, my, slot & 31);
            if (slot < cnt) {
                uint4 v = __ldg(&rows[src * 4 + c]);
                float2 f0 = __half22float2(*reinterpret_cast<__half2*>(&v.x));
                float2 f1 = __half22float2(*reinterpret_cast<__half2*>(&v.y));
                float2 f2 = __half22float2(*reinterpret_cast<__half2*>(&v.z));
                float2 f3 = __half22float2(*reinterpret_cast<__half2*>(&v.w));
                acc[0] += f0.x; acc[1] += f0.y; acc[2] += f1.x; acc[3] += f1.y;
                acc[4] += f2.x; acc[5] += f2.y; acc[6] += f3.x; acc[7] += f3.y;
            }
        }
    }
#pragma unroll
    for (int o = 4; o <= 16; o <<= 1)
#pragma unroll
        for (int k = 0; k < 8; k++)
            acc[k] += __shfl_xor_sync(full, acc[k], o);
}

// ---------------- prop: T1 = L~ x ; warp per row ----------------
__global__ void k_prop(int in_id, int n) {
    const uint4* __restrict__ xh = hbuf(in_id);
    int w = (blockIdx.x * blockDim.x + threadIdx.x) >> 5;
    int lane = threadIdx.x & 31;
    if (w >= n) return;
    int s = g_off[w], e = g_off[w + 1];
    float acc[8] = {0.f, 0.f, 0.f, 0.f, 0.f, 0.f, 0.f, 0.f};
    gather8(xh, s, e, lane, acc);
    if (lane < 4) {
        float di = g_dinv[w];
        float r[8];
#pragma unroll
        for (int k = 0; k < 8; k++) r[k] = -di * acc[k];
        g_t[w * 8 + lane * 2]     = make_float4(r[0], r[1], r[2], r[3]);
        g_t[w * 8 + lane * 2 + 1] = make_float4(r[4], r[5], r[6], r[7]);
        __half2 h0 = __floats2half2_rn(di * r[0], di * r[1]);
        __half2 h1 = __floats2half2_rn(di * r[2], di * r[3]);
        __half2 h2 = __floats2half2_rn(di * r[4], di * r[5]);
        __half2 h3 = __floats2half2_rn(di * r[6], di * r[7]);
        uint4 sh;
        sh.x = *reinterpret_cast<unsigned*>(&h0);
        sh.y = *reinterpret_cast<unsigned*>(&h1);
        sh.z = *reinterpret_cast<unsigned*>(&h2);
        sh.w = *reinterpret_cast<unsigned*>(&h3);
        s_t[w * 4 + lane] = sh;
    }
}

// ---------------- fused second prop + tiled Chebyshev combine ----------------
__global__ void __launch_bounds__(256) k_comb(int t0_id, int resid_id, int out_id,
                       const float* __restrict__ Wc, const float* __restrict__ bc, int n) {
    __shared__ float sT[32][100];
    __shared__ float sWt[32][100];
    __shared__ float sO[32][33];
    const float4* __restrict__ t0f = fbuf(t0_id);
    float4* __restrict__ outf = fbuf(out_id);
    uint2* __restrict__ outsh = (uint2*)hbuf(out_id);

    int tid = threadIdx.x;
    int wid = tid >> 5, lane = tid & 31;
    int base = blockIdx.x << 5;

#pragma unroll
    for (int rep = 0; rep < 12; rep++) {
        int idx = rep * 256 + tid;
        sWt[idx & 31][idx >> 5] = Wc[idx];
    }

    // gather phase: warp wid handles nodes base + wid*4 + j
#pragma unroll
    for (int j = 0; j < 4; j++) {
        int nl = (wid << 2) + j;
        int node = base + nl;
        if (node < n) {
            int s = g_off[node], e = g_off[node + 1];
            float acc[8] = {0.f, 0.f, 0.f, 0.f, 0.f, 0.f, 0.f, 0.f};
            gather8(s_t, s, e, lane, acc);
            if (lane < 4) {
                float di = g_dinv[node];
                float4 t0a = t0f[node * 8 + lane * 2];
                float4 t0b = t0f[node * 8 + lane * 2 + 1];
                float4 t1a = g_t[node * 8 + lane * 2];
                float4 t1b = g_t[node * 8 + lane * 2 + 1];
                float4 t2a, t2b;
                float m = -2.f * di;
                t2a.x = fmaf(m, acc[0], -t0a.x); t2a.y = fmaf(m, acc[1], -t0a.y);
                t2a.z = fmaf(m, acc[2], -t0a.z); t2a.w = fmaf(m, acc[3], -t0a.w);
                t2b.x = fmaf(m, acc[4], -t0b.x); t2b.y = fmaf(m, acc[5], -t0b.y);
                t2b.z = fmaf(m, acc[6], -t0b.z); t2b.w = fmaf(m, acc[7], -t0b.w);
                *(float4*)&sT[nl][lane * 8]          = t0a;
                *(float4*)&sT[nl][lane * 8 + 4]      = t0b;
                *(float4*)&sT[nl][32 + lane * 8]     = t1a;
                *(float4*)&sT[nl][32 + lane * 8 + 4] = t1b;
                *(float4*)&sT[nl][64 + lane * 8]     = t2a;
                *(float4*)&sT[nl][64 + lane * 8 + 4] = t2b;
            }
        }
    }
    __syncthreads();

    // dense phase: warp wid -> features {wid, wid+8, wid+16, wid+24}, node = lane
    {
        float acc0 = __ldg(&bc[wid]);
        float acc1 = __ldg(&bc[wid + 8]);
        float acc2 = __ldg(&bc[wid + 16]);
        float acc3 = __ldg(&bc[wid + 24]);
#pragma unroll
        for (int kc = 0; kc < 24; kc++) {
            float4 t = *(const float4*)&sT[lane][kc * 4];
            float4 w0 = *(const float4*)&sWt[wid][kc * 4];
            float4 w1 = *(const float4*)&sWt[wid + 8][kc * 4];
            float4 w2 = *(const float4*)&sWt[wid + 16][kc * 4];
            float4 w3 = *(const float4*)&sWt[wid + 24][kc * 4];
            acc0 += t.x * w0.x + t.y * w0.y + t.z * w0.z + t.w * w0.w;
            acc1 += t.x * w1.x + t.y * w1.y + t.z * w1.z + t.w * w1.w;
            acc2 += t.x * w2.x + t.y * w2.y + t.z * w2.z + t.w * w2.w;
            acc3 += t.x * w3.x + t.y * w3.y + t.z * w3.z + t.w * w3.w;
        }
        sO[lane][wid]      = acc0;
        sO[lane][wid + 8]  = acc1;
        sO[lane][wid + 16] = acc2;
        sO[lane][wid + 24] = acc3;
    }
    __syncthreads();

    // epilogue
    {
        int nl = tid >> 3, cc = tid & 7;
        int node = base + nl;
        if (node < n) {
            float4 o;
            o.x = sO[nl][cc * 4 + 0];
            o.y = sO[nl][cc * 4 + 1];
            o.z = sO[nl][cc * 4 + 2];
            o.w = sO[nl][cc * 4 + 3];
            if (resid_id >= 0) {
                float4 rv = fbuf(resid_id)[node * 8 + cc];
                o.x += rv.x; o.y += rv.y; o.z += rv.z; o.w += rv.w;
            }
            o.x = fmaxf(o.x, 0.f); o.y = fmaxf(o.y, 0.f);
            o.z = fmaxf(o.z, 0.f); o.w = fmaxf(o.w, 0.f);
            outf[node * 8 + cc] = o;
            float di = g_dinv[node];
            __half2 ha = __floats2half2_rn(di * o.x, di * o.y);
            __half2 hb = __floats2half2_rn(di * o.z, di * o.w);
            uint2 sh;
            sh.x = *reinterpret_cast<unsigned*>(&ha);
            sh.y = *reinterpret_cast<unsigned*>(&hb);
            outsh[node * 8 + cc] = sh;
        }
    }
}

// ---------------- output layer ----------------
__global__ void k_final(const float* __restrict__ W1, const float* __restrict__ b1,
                        float* __restrict__ out, int n) {
    int node = (blockIdx.x * blockDim.x + threadIdx.x) >> 5;
    int lane = threadIdx.x & 31;
    if (node >= n) return;
    float v = ((const float*)g_h)[node * 32 + lane] * W1[lane];
#pragma unroll
    for (int o = 16; o > 0; o >>= 1) v += __shfl_xor_sync(0xffffffffu, v, o);
    if (lane == 0) out[node] = v + b1[0];
}

// ---------------- launch ----------------
extern "C" void kernel_launch(void* const* d_in, const int* in_sizes, int n_in,
                              void* d_out, int out_size) {
    const float* x    = (const float*)d_in[0];
    const void*  ei   = d_in[1];
    const float* W0   = (const float*)d_in[2];
    const float* b0   = (const float*)d_in[3];
    const float* c11W = (const float*)d_in[4];
    const float* c11b = (const float*)d_in[5];
    const float* c12W = (const float*)d_in[6];
    const float* c12b = (const float*)d_in[7];
    const float* c21W = (const float*)d_in[8];
    const float* c21b = (const float*)d_in[9];
    const float* c22W = (const float*)d_in[10];
    const float* c22b = (const float*)d_in[11];
    const float* W1   = (const float*)d_in[12];
    const float* b1   = (const float*)d_in[13];
    float* out = (float*)d_out;

    int n = in_sizes[0] / 3;
    int e = in_sizes[1] / 2;
    if (n > NN) n = NN;
    if (e > EE) e = EE;

    const int B = 256;
    int gN  = (n + B - 1) / B;
    int gE  = (e + B - 1) / B;
    int gNF = (n * 32 + B - 1) / B;
    int gT  = (n + 31) / 32;
    int nb  = (n + 1023) / 1024;
    int gSI = (n * 32 > e ? n * 32 : e);
    gSI = (gSI + B - 1) / B;

    // setup: 5 launches, so first k_prop is launch #6 (ncu -s 5 captures it)
    k_dz<<<gN, B>>>(ei, n);
    k_count<<<gE, B>>>(ei, e);
    k_scan1<<<nb, 1024>>>(n);
    k_scan23<<<nb, 1024>>>(n);
    k_scatin<<<gSI, B>>>(ei, e, x, W0, b0, n);

    // ids: 0=h, 1=a, 2=t, 3=b
    k_prop<<<gNF, B>>>(0, n);
    k_comb<<<gT, B>>>(0, -1, 1, c11W, c11b, n);
    k_prop<<<gNF, B>>>(1, n);
    k_comb<<<gT, B>>>(1, 0, 3, c12W, c12b, n);
    k_prop<<<gNF, B>>>(3, n);
    k_comb<<<gT, B>>>(3, -1, 1, c21W, c21b, n);
    k_prop<<<gNF, B>>>(1, n);
    k_comb<<<gT, B>>>(1, 3, 0, c22W, c22b, n);

    k_final<<<gNF, B>>>(W1, b1, out, n);
}

// round 6
// speedup vs baseline: 1.0422x; 1.0422x over previous
#include <cuda_runtime.h>
#include <cuda_fp16.h>

#define NN 200000
#define EE 3200000

// ---------------- static device scratch ----------------
__device__ int      g_deg[NN];
__device__ int      g_cnt[NN];
__device__ float    g_dinv[NN];
__device__ int      g_off[NN + 1];
__device__ int      g_cur[NN];
__device__ unsigned long long g_aggr64[256];   // gen-tagged block aggregates
__device__ unsigned g_gen;
__device__ int      g_src[EE];
__device__ float4   g_h[NN * 8];
__device__ float4   g_a[NN * 8];
__device__ float4   g_t[NN * 8];
__device__ float4   g_b[NN * 8];
__device__ uint4    s_h[NN * 4];   // fp16 shadows (pre-scaled by dinv)
__device__ uint4    s_a[NN * 4];
__device__ uint4    s_t[NN * 4];
__device__ uint4    s_b[NN * 4];

__device__ __forceinline__ float4* fbuf(int id) {
    switch (id) { case 0: return g_h; case 1: return g_a; case 2: return g_t; default: return g_b; }
}
__device__ __forceinline__ uint4* hbuf(int id) {
    switch (id) { case 0: return s_h; case 1: return s_a; case 2: return s_t; default: return s_b; }
}

// per-block dtype detection: returns 1 if edge buffer is int64
__device__ __forceinline__ int detect64(const void* ei) {
    const int* w = (const int*)ei;
    int bad = 0;
#pragma unroll
    for (int k = 0; k < 2; k++) {
        int idx = (threadIdx.x & 31) + 32 * k;
        if (w[2 * idx + 1] != 0) bad = 1;
    }
    return __all_sync(0xffffffffu, bad == 0) ? 1 : 0;
}

__device__ __forceinline__ int edge_at(const void* ei, int idx, int is64) {
    if (is64) return (int)((const long long*)ei)[idx];
    return ((const int*)ei)[idx];
}

// ---------------- count degrees (g_deg/g_cnt pre-zeroed: static init or prior k_scan) ----------------
__global__ void k_count(const void* ei, int e) {
    if (blockIdx.x == 0 && threadIdx.x == 0) atomicAdd(&g_gen, 1u);
    int is64 = detect64(ei);
    int i = blockIdx.x * blockDim.x + threadIdx.x;
    if (i < e) {
        int s = edge_at(ei, i, is64);
        int d = edge_at(ei, e + i, is64);
        atomicAdd(&g_deg[s], 1);
        atomicAdd(&g_cnt[d], 1);
    }
}

// ---------------- single-kernel exclusive scan (decoupled lookback) + dinv + reset ----------------
__global__ void k_scan(int n, int nb) {
    __shared__ int sh[1024];
    __shared__ int s_sum;
    int tid = threadIdx.x, b = blockIdx.x;
    int i = b * 1024 + tid;
    if (tid == 0) s_sum = 0;
    int dg = 0, v = 0;
    if (i < n) { dg = g_deg[i]; v = g_cnt[i]; }
    if (i < n) g_dinv[i] = (dg > 0) ? rsqrtf((float)dg) : 0.f;
    sh[tid] = v;
    __syncthreads();
    for (int o = 1; o < 1024; o <<= 1) {
        int t = (tid >= o) ? sh[tid - o] : 0;
        __syncthreads();
        sh[tid] += t;
        __syncthreads();
    }
    unsigned gen = g_gen;
    if (tid == 1023)   // publish gen-tagged aggregate
        atomicExch(&g_aggr64[b], ((unsigned long long)gen << 32) | (unsigned)sh[1023]);
    if (tid < b) {     // parallel predecessor sum
        unsigned long long f;
        while (((f = atomicAdd(&g_aggr64[tid], 0ull)) >> 32) != gen) {}
        atomicAdd(&s_sum, (int)(unsigned)f);
    }
    __syncthreads();
    int off = sh[tid] - v + s_sum;   // global exclusive prefix
    if (i < n) {
        g_off[i] = off;
        g_cur[i] = off;
        g_deg[i] = 0;     // reset for next replay
        g_cnt[i] = 0;
        if (i == n - 1) g_off[n] = off + v;
    }
}

// ---------------- fused scatter (i < e) + input MLP (i < n*32) ----------------
__global__ void k_scatin(const void* ei, int e, const float* __restrict__ x,
                         const float* __restrict__ W0, const float* __restrict__ b0, int n) {
    __shared__ float sw[96];
    __shared__ float sb[32];
    int tid = threadIdx.x;
    int is64 = detect64(ei);
    if (tid < 96) sw[tid] = W0[tid];
    if (tid < 32) sb[tid] = b0[tid];
    __syncthreads();
    int i = blockIdx.x * blockDim.x + tid;
    if (i < e) {
        int s = edge_at(ei, i, is64);
        int d = edge_at(ei, e + i, is64);
        int p = atomicAdd(&g_cur[d], 1);
        g_src[p] = s;
    }
    if (i < n * 32) {
        int node = i >> 5, f = i & 31;
        float x0 = x[node * 3 + 0];
        float x1 = x[node * 3 + 1];
        float x2 = x[node * 3 + 2];
        float o = sb[f] + x0 * sw[f] + x1 * sw[32 + f] + x2 * sw[64 + f];
        o = fmaxf(o, 0.f);
        ((float*)g_h)[i] = o;
        float di = g_dinv[node];
        float o_hi = __shfl_down_sync(0xffffffffu, o, 1);
        if ((f & 1) == 0)
            ((__half2*)s_h)[node * 16 + (f >> 1)] = __floats2half2_rn(di * o, di * o_hi);
    }
}

// -------- gather v3: 8 groups x uint4; 32-edge batches, statically unrolled, no shfl in path --------
// After reduction every lane holds features c*8..c*8+7 (c = lane&3) of the row sum.
__device__ __forceinline__ void gatherRow(const uint4* __restrict__ rows,
                                          int s, int e, int lane, float acc[8]) {
    int g = lane >> 2, c = lane & 3;
    const unsigned full = 0xffffffffu;
    for (int base = s; base < e; base += 32) {
        int cnt = e - base;
        int src[4];
#pragma unroll
        for (int k = 0; k < 4; k++) {
            int off = g + 8 * k;
            src[k] = (off < cnt) ? __ldg(&g_src[base + off]) : -1;
        }
#pragma unroll
        for (int k = 0; k < 4; k++) {
            if (src[k] >= 0) {
                uint4 v = __ldg(&rows[src[k] * 4 + c]);
                float2 f0 = __half22float2(*reinterpret_cast<__half2*>(&v.x));
                float2 f1 = __half22float2(*reinterpret_cast<__half2*>(&v.y));
                float2 f2 = __half22float2(*reinterpret_cast<__half2*>(&v.z));
                float2 f3 = __half22float2(*reinterpret_cast<__half2*>(&v.w));
                acc[0] += f0.x; acc[1] += f0.y; acc[2] += f1.x; acc[3] += f1.y;
                acc[4] += f2.x; acc[5] += f2.y; acc[6] += f3.x; acc[7] += f3.y;
            }
        }
    }
#pragma unroll
    for (int o = 4; o <= 16; o <<= 1)
#pragma unroll
        for (int k = 0; k < 8; k++)
            acc[k] += __shfl_xor_sync(full, acc[k], o);
}

// ---------------- prop: T1 = L~ x ; warp per row ----------------
__global__ void k_prop(int in_id, int n) {
    const uint4* __restrict__ xh = hbuf(in_id);
    int w = (blockIdx.x * blockDim.x + threadIdx.x) >> 5;
    int lane = threadIdx.x & 31;
    if (w >= n) return;
    int s = g_off[w], e = g_off[w + 1];
    float acc[8] = {0.f, 0.f, 0.f, 0.f, 0.f, 0.f, 0.f, 0.f};
    gatherRow(xh, s, e, lane, acc);
    if (lane < 4) {
        float di = g_dinv[w];
        float r[8];
#pragma unroll
        for (int k = 0; k < 8; k++) r[k] = -di * acc[k];
        g_t[w * 8 + lane * 2]     = make_float4(r[0], r[1], r[2], r[3]);
        g_t[w * 8 + lane * 2 + 1] = make_float4(r[4], r[5], r[6], r[7]);
        __half2 h0 = __floats2half2_rn(di * r[0], di * r[1]);
        __half2 h1 = __floats2half2_rn(di * r[2], di * r[3]);
        __half2 h2 = __floats2half2_rn(di * r[4], di * r[5]);
        __half2 h3 = __floats2half2_rn(di * r[6], di * r[7]);
        uint4 sh;
        sh.x = *reinterpret_cast<unsigned*>(&h0);
        sh.y = *reinterpret_cast<unsigned*>(&h1);
        sh.z = *reinterpret_cast<unsigned*>(&h2);
        sh.w = *reinterpret_cast<unsigned*>(&h3);
        s_t[w * 4 + lane] = sh;
    }
}

// ---------------- fused second prop + tiled Chebyshev combine ----------------
__global__ void __launch_bounds__(256) k_comb(int t0_id, int resid_id, int out_id,
                       const float* __restrict__ Wc, const float* __restrict__ bc, int n) {
    __shared__ float sT[32][100];
    __shared__ float sWt[32][100];
    __shared__ float sO[32][33];
    const float4* __restrict__ t0f = fbuf(t0_id);
    float4* __restrict__ outf = fbuf(out_id);
    uint2* __restrict__ outsh = (uint2*)hbuf(out_id);

    int tid = threadIdx.x;
    int wid = tid >> 5, lane = tid & 31;
    int base = blockIdx.x << 5;

#pragma unroll
    for (int rep = 0; rep < 12; rep++) {
        int idx = rep * 256 + tid;
        sWt[idx & 31][idx >> 5] = Wc[idx];
    }

    // gather phase: warp wid handles nodes base + wid*4 + j
#pragma unroll
    for (int j = 0; j < 4; j++) {
        int nl = (wid << 2) + j;
        int node = base + nl;
        if (node < n) {
            int s = g_off[node], e = g_off[node + 1];
            float acc[8] = {0.f, 0.f, 0.f, 0.f, 0.f, 0.f, 0.f, 0.f};
            gatherRow(s_t, s, e, lane, acc);
            if (lane < 4) {
                float di = g_dinv[node];
                float4 t0a = t0f[node * 8 + lane * 2];
                float4 t0b = t0f[node * 8 + lane * 2 + 1];
                float4 t1a = g_t[node * 8 + lane * 2];
                float4 t1b = g_t[node * 8 + lane * 2 + 1];
                float4 t2a, t2b;
                float m = -2.f * di;
                t2a.x = fmaf(m, acc[0], -t0a.x); t2a.y = fmaf(m, acc[1], -t0a.y);
                t2a.z = fmaf(m, acc[2], -t0a.z); t2a.w = fmaf(m, acc[3], -t0a.w);
                t2b.x = fmaf(m, acc[4], -t0b.x); t2b.y = fmaf(m, acc[5], -t0b.y);
                t2b.z = fmaf(m, acc[6], -t0b.z); t2b.w = fmaf(m, acc[7], -t0b.w);
                *(float4*)&sT[nl][lane * 8]          = t0a;
                *(float4*)&sT[nl][lane * 8 + 4]      = t0b;
                *(float4*)&sT[nl][32 + lane * 8]     = t1a;
                *(float4*)&sT[nl][32 + lane * 8 + 4] = t1b;
                *(float4*)&sT[nl][64 + lane * 8]     = t2a;
                *(float4*)&sT[nl][64 + lane * 8 + 4] = t2b;
            }
        }
    }
    __syncthreads();

    // dense phase: warp wid -> features {wid, wid+8, wid+16, wid+24}, node = lane
    {
        float acc0 = __ldg(&bc[wid]);
        float acc1 = __ldg(&bc[wid + 8]);
        float acc2 = __ldg(&bc[wid + 16]);
        float acc3 = __ldg(&bc[wid + 24]);
#pragma unroll
        for (int kc = 0; kc < 24; kc++) {
            float4 t = *(const float4*)&sT[lane][kc * 4];
            float4 w0 = *(const float4*)&sWt[wid][kc * 4];
            float4 w1 = *(const float4*)&sWt[wid + 8][kc * 4];
            float4 w2 = *(const float4*)&sWt[wid + 16][kc * 4];
            float4 w3 = *(const float4*)&sWt[wid + 24][kc * 4];
            acc0 += t.x * w0.x + t.y * w0.y + t.z * w0.z + t.w * w0.w;
            acc1 += t.x * w1.x + t.y * w1.y + t.z * w1.z + t.w * w1.w;
            acc2 += t.x * w2.x + t.y * w2.y + t.z * w2.z + t.w * w2.w;
            acc3 += t.x * w3.x + t.y * w3.y + t.z * w3.z + t.w * w3.w;
        }
        sO[lane][wid]      = acc0;
        sO[lane][wid + 8]  = acc1;
        sO[lane][wid + 16] = acc2;
        sO[lane][wid + 24] = acc3;
    }
    __syncthreads();

    // epilogue
    {
        int nl = tid >> 3, cc = tid & 7;
        int node = base + nl;
        if (node < n) {
            float4 o;
            o.x = sO[nl][cc * 4 + 0];
            o.y = sO[nl][cc * 4 + 1];
            o.z = sO[nl][cc * 4 + 2];
            o.w = sO[nl][cc * 4 + 3];
            if (resid_id >= 0) {
                float4 rv = fbuf(resid_id)[node * 8 + cc];
                o.x += rv.x; o.y += rv.y; o.z += rv.z; o.w += rv.w;
            }
            o.x = fmaxf(o.x, 0.f); o.y = fmaxf(o.y, 0.f);
            o.z = fmaxf(o.z, 0.f); o.w = fmaxf(o.w, 0.f);
            outf[node * 8 + cc] = o;
            float di = g_dinv[node];
            __half2 ha = __floats2half2_rn(di * o.x, di * o.y);
            __half2 hb = __floats2half2_rn(di * o.z, di * o.w);
            uint2 sh;
            sh.x = *reinterpret_cast<unsigned*>(&ha);
            sh.y = *reinterpret_cast<unsigned*>(&hb);
            outsh[node * 8 + cc] = sh;
        }
    }
}

// ---------------- output layer ----------------
__global__ void k_final(const float* __restrict__ W1, const float* __restrict__ b1,
                        float* __restrict__ out, int n) {
    int node = (blockIdx.x * blockDim.x + threadIdx.x) >> 5;
    int lane = threadIdx.x & 31;
    if (node >= n) return;
    float v = ((const float*)g_h)[node * 32 + lane] * W1[lane];
#pragma unroll
    for (int o = 16; o > 0; o >>= 1) v += __shfl_xor_sync(0xffffffffu, v, o);
    if (lane == 0) out[node] = v + b1[0];
}

// ---------------- launch ----------------
extern "C" void kernel_launch(void* const* d_in, const int* in_sizes, int n_in,
                              void* d_out, int out_size) {
    const float* x    = (const float*)d_in[0];
    const void*  ei   = d_in[1];
    const float* W0   = (const float*)d_in[2];
    const float* b0   = (const float*)d_in[3];
    const float* c11W = (const float*)d_in[4];
    const float* c11b = (const float*)d_in[5];
    const float* c12W = (const float*)d_in[6];
    const float* c12b = (const float*)d_in[7];
    const float* c21W = (const float*)d_in[8];
    const float* c21b = (const float*)d_in[9];
    const float* c22W = (const float*)d_in[10];
    const float* c22b = (const float*)d_in[11];
    const float* W1   = (const float*)d_in[12];
    const float* b1   = (const float*)d_in[13];
    float* out = (float*)d_out;

    int n = in_sizes[0] / 3;
    int e = in_sizes[1] / 2;
    if (n > NN) n = NN;
    if (e > EE) e = EE;

    const int B = 256;
    int gE  = (e + B - 1) / B;
    int gNF = (n * 32 + B - 1) / B;
    int gT  = (n + 31) / 32;
    int nb  = (n + 1023) / 1024;
    int gSI = (n * 32 > e ? n * 32 : e);
    gSI = (gSI + B - 1) / B;

    // setup: 3 launches -> first k_prop is launch #4 (ncu capture target)
    k_count<<<gE, B>>>(ei, e);
    k_scan<<<nb, 1024>>>(n, nb);
    k_scatin<<<gSI, B>>>(ei, e, x, W0, b0, n);

    // ids: 0=h, 1=a, 2=t, 3=b
    k_prop<<<gNF, B>>>(0, n);
    k_comb<<<gT, B>>>(0, -1, 1, c11W, c11b, n);
    k_prop<<<gNF, B>>>(1, n);
    k_comb<<<gT, B>>>(1, 0, 3, c12W, c12b, n);
    k_prop<<<gNF, B>>>(3, n);
    k_comb<<<gT, B>>>(3, -1, 1, c21W, c21b, n);
    k_prop<<<gNF, B>>>(1, n);
    k_comb<<<gT, B>>>(1, 3, 0, c22W, c22b, n);

    k_final<<<gNF, B>>>(W1, b1, out, n);
}

// round 7
// speedup vs baseline: 1.2211x; 1.1717x over previous
#include <cuda_runtime.h>

#define NN 200000
#define EE 3200000

// ---------------- static device scratch ----------------
__device__ int      g_deg[NN];
__device__ int      g_cnt[NN];
__device__ float    g_dinv[NN];
__device__ int      g_off[NN + 1];
__device__ int      g_cur[NN];
__device__ unsigned long long g_aggr64[256];
__device__ unsigned g_gen;
__device__ int      g_src[EE];
__device__ float4   g_h[NN * 8];   // raw fp32 features
__device__ float4   g_a[NN * 8];
__device__ float4   g_t[NN * 8];
__device__ float4   g_b[NN * 8];
__device__ float4   p_h[NN * 8];   // pre-scaled (dinv * X) fp32
__device__ float4   p_a[NN * 8];
__device__ float4   p_t[NN * 8];
__device__ float4   p_b[NN * 8];

__device__ __forceinline__ float4* fbuf(int id) {
    switch (id) { case 0: return g_h; case 1: return g_a; case 2: return g_t; default: return g_b; }
}
__device__ __forceinline__ float4* pbuf(int id) {
    switch (id) { case 0: return p_h; case 1: return p_a; case 2: return p_t; default: return p_b; }
}

// per-block dtype detection: 1 if edge buffer is int64
__device__ __forceinline__ int detect64(const void* ei) {
    const int* w = (const int*)ei;
    int bad = 0;
#pragma unroll
    for (int k = 0; k < 2; k++) {
        int idx = (threadIdx.x & 31) + 32 * k;
        if (w[2 * idx + 1] != 0) bad = 1;
    }
    return __all_sync(0xffffffffu, bad == 0) ? 1 : 0;
}

__device__ __forceinline__ int edge_at(const void* ei, int idx, int is64) {
    if (is64) return (int)((const long long*)ei)[idx];
    return ((const int*)ei)[idx];
}

// ---------------- count degrees ----------------
__global__ void k_count(const void* ei, int e) {
    if (blockIdx.x == 0 && threadIdx.x == 0) atomicAdd(&g_gen, 1u);
    int is64 = detect64(ei);
    int i = blockIdx.x * blockDim.x + threadIdx.x;
    if (i < e) {
        int s = edge_at(ei, i, is64);
        int d = edge_at(ei, e + i, is64);
        atomicAdd(&g_deg[s], 1);
        atomicAdd(&g_cnt[d], 1);
    }
}

// ---------------- one-kernel exclusive scan + dinv + reset ----------------
__global__ void k_scan(int n, int nb) {
    __shared__ int sh[1024];
    __shared__ int s_sum;
    int tid = threadIdx.x, b = blockIdx.x;
    int i = b * 1024 + tid;
    if (tid == 0) s_sum = 0;
    int dg = 0, v = 0;
    if (i < n) { dg = g_deg[i]; v = g_cnt[i]; }
    if (i < n) g_dinv[i] = (dg > 0) ? rsqrtf((float)dg) : 0.f;
    sh[tid] = v;
    __syncthreads();
    for (int o = 1; o < 1024; o <<= 1) {
        int t = (tid >= o) ? sh[tid - o] : 0;
        __syncthreads();
        sh[tid] += t;
        __syncthreads();
    }
    unsigned gen = g_gen;
    if (tid == 1023)
        atomicExch(&g_aggr64[b], ((unsigned long long)gen << 32) | (unsigned)sh[1023]);
    if (tid < b) {
        unsigned long long f;
        while (((f = atomicAdd(&g_aggr64[tid], 0ull)) >> 32) != gen) {}
        atomicAdd(&s_sum, (int)(unsigned)f);
    }
    __syncthreads();
    int off = sh[tid] - v + s_sum;
    if (i < n) {
        g_off[i] = off;
        g_cur[i] = off;
        g_deg[i] = 0;
        g_cnt[i] = 0;
        if (i == n - 1) g_off[n] = off + v;
    }
}

// ---------------- fused scatter + input MLP ----------------
__global__ void k_scatin(const void* ei, int e, const float* __restrict__ x,
                         const float* __restrict__ W0, const float* __restrict__ b0, int n) {
    __shared__ float sw[96];
    __shared__ float sb[32];
    int tid = threadIdx.x;
    int is64 = detect64(ei);
    if (tid < 96) sw[tid] = W0[tid];
    if (tid < 32) sb[tid] = b0[tid];
    __syncthreads();
    int i = blockIdx.x * blockDim.x + tid;
    if (i < e) {
        int s = edge_at(ei, i, is64);
        int d = edge_at(ei, e + i, is64);
        int p = atomicAdd(&g_cur[d], 1);
        g_src[p] = s;
    }
    if (i < n * 32) {
        int node = i >> 5, f = i & 31;
        float x0 = x[node * 3 + 0];
        float x1 = x[node * 3 + 1];
        float x2 = x[node * 3 + 2];
        float o = sb[f] + x0 * sw[f] + x1 * sw[32 + f] + x2 * sw[64 + f];
        o = fmaxf(o, 0.f);
        ((float*)g_h)[i] = o;
        ((float*)p_h)[i] = g_dinv[node] * o;
    }
}

// -------- group gather: 8-lane group accumulates ONE row, lane = float4 chunk c --------
__device__ __forceinline__ float4 gatherG(const float4* __restrict__ rows,
                                          int s, int e, int c) {
    float4 acc = make_float4(0.f, 0.f, 0.f, 0.f);
    int i = s;
    for (; i + 4 <= e; i += 4) {
        int s0 = __ldg(&g_src[i]);
        int s1 = __ldg(&g_src[i + 1]);
        int s2 = __ldg(&g_src[i + 2]);
        int s3 = __ldg(&g_src[i + 3]);
        float4 v0 = __ldg(&rows[s0 * 8 + c]);
        float4 v1 = __ldg(&rows[s1 * 8 + c]);
        float4 v2 = __ldg(&rows[s2 * 8 + c]);
        float4 v3 = __ldg(&rows[s3 * 8 + c]);
        acc.x += (v0.x + v1.x) + (v2.x + v3.x);
        acc.y += (v0.y + v1.y) + (v2.y + v3.y);
        acc.z += (v0.z + v1.z) + (v2.z + v3.z);
        acc.w += (v0.w + v1.w) + (v2.w + v3.w);
    }
    for (; i < e; i++) {
        int s0 = __ldg(&g_src[i]);
        float4 v = __ldg(&rows[s0 * 8 + c]);
        acc.x += v.x; acc.y += v.y; acc.z += v.z; acc.w += v.w;
    }
    return acc;
}

// ---------------- prop: T1 = L~ x ; warp = 4 rows, 8-lane group per row ----------------
__global__ void k_prop(int in_id, int n) {
    const float4* __restrict__ xin = pbuf(in_id);
    int t = blockIdx.x * blockDim.x + threadIdx.x;
    int lane = threadIdx.x & 31;
    int row = ((t >> 5) << 2) + (lane >> 3);
    int c = lane & 7;
    if (row >= n) return;
    int s = g_off[row], e = g_off[row + 1];
    float4 acc = gatherG(xin, s, e, c);
    float di = g_dinv[row];
    float4 r = make_float4(-di * acc.x, -di * acc.y, -di * acc.z, -di * acc.w);
    g_t[row * 8 + c] = r;
    p_t[row * 8 + c] = make_float4(di * r.x, di * r.y, di * r.z, di * r.w);
}

// ---------------- fused second prop + tiled Chebyshev combine ----------------
__global__ void __launch_bounds__(256) k_comb(int t0_id, int resid_id, int out_id,
                       const float* __restrict__ Wc, const float* __restrict__ bc, int n) {
    __shared__ float sT[32][100];
    __shared__ float sWt[32][100];
    __shared__ float sO[32][33];
    const float4* __restrict__ t0f = fbuf(t0_id);
    float4* __restrict__ outf = fbuf(out_id);
    float4* __restrict__ outp = pbuf(out_id);

    int tid = threadIdx.x;
    int wid = tid >> 5, lane = tid & 31;
    int base = blockIdx.x << 5;

#pragma unroll
    for (int rep = 0; rep < 12; rep++) {
        int idx = rep * 256 + tid;
        sWt[idx & 31][idx >> 5] = Wc[idx];
    }

    // gather phase: warp's 4 groups = 4 nodes
    {
        int grp = lane >> 3, c = lane & 7;
        int nl = (wid << 2) + grp;
        int node = base + nl;
        if (node < n) {
            int s = g_off[node], e = g_off[node + 1];
            float4 acc = gatherG(p_t, s, e, c);
            float di = g_dinv[node];
            float4 t0 = t0f[node * 8 + c];
            float4 t1 = g_t[node * 8 + c];
            float m = -2.f * di;
            float4 t2;
            t2.x = fmaf(m, acc.x, -t0.x);
            t2.y = fmaf(m, acc.y, -t0.y);
            t2.z = fmaf(m, acc.z, -t0.z);
            t2.w = fmaf(m, acc.w, -t0.w);
            *(float4*)&sT[nl][c * 4]      = t0;
            *(float4*)&sT[nl][32 + c * 4] = t1;
            *(float4*)&sT[nl][64 + c * 4] = t2;
        }
    }
    __syncthreads();

    // dense phase: warp wid -> features {wid, wid+8, wid+16, wid+24}, node = lane
    {
        float acc0 = __ldg(&bc[wid]);
        float acc1 = __ldg(&bc[wid + 8]);
        float acc2 = __ldg(&bc[wid + 16]);
        float acc3 = __ldg(&bc[wid + 24]);
#pragma unroll
        for (int kc = 0; kc < 24; kc++) {
            float4 t = *(const float4*)&sT[lane][kc * 4];
            float4 w0 = *(const float4*)&sWt[wid][kc * 4];
            float4 w1 = *(const float4*)&sWt[wid + 8][kc * 4];
            float4 w2 = *(const float4*)&sWt[wid + 16][kc * 4];
            float4 w3 = *(const float4*)&sWt[wid + 24][kc * 4];
            acc0 += t.x * w0.x + t.y * w0.y + t.z * w0.z + t.w * w0.w;
            acc1 += t.x * w1.x + t.y * w1.y + t.z * w1.z + t.w * w1.w;
            acc2 += t.x * w2.x + t.y * w2.y + t.z * w2.z + t.w * w2.w;
            acc3 += t.x * w3.x + t.y * w3.y + t.z * w3.z + t.w * w3.w;
        }
        sO[lane][wid]      = acc0;
        sO[lane][wid + 8]  = acc1;
        sO[lane][wid + 16] = acc2;
        sO[lane][wid + 24] = acc3;
    }
    __syncthreads();

    // epilogue: resid + relu + raw/prescaled stores
    {
        int nl = tid >> 3, cc = tid & 7;
        int node = base + nl;
        if (node < n) {
            float4 o;
            o.x = sO[nl][cc * 4 + 0];
            o.y = sO[nl][cc * 4 + 1];
            o.z = sO[nl][cc * 4 + 2];
            o.w = sO[nl][cc * 4 + 3];
            if (resid_id >= 0) {
                float4 rv = fbuf(resid_id)[node * 8 + cc];
                o.x += rv.x; o.y += rv.y; o.z += rv.z; o.w += rv.w;
            }
            o.x = fmaxf(o.x, 0.f); o.y = fmaxf(o.y, 0.f);
            o.z = fmaxf(o.z, 0.f); o.w = fmaxf(o.w, 0.f);
            outf[node * 8 + cc] = o;
            float di = g_dinv[node];
            outp[node * 8 + cc] = make_float4(di * o.x, di * o.y, di * o.z, di * o.w);
        }
    }
}

// ---------------- output layer ----------------
__global__ void k_final(const float* __restrict__ W1, const float* __restrict__ b1,
                        float* __restrict__ out, int n) {
    int node = (blockIdx.x * blockDim.x + threadIdx.x) >> 5;
    int lane = threadIdx.x & 31;
    if (node >= n) return;
    float v = ((const float*)g_h)[node * 32 + lane] * W1[lane];
#pragma unroll
    for (int o = 16; o > 0; o >>= 1) v += __shfl_xor_sync(0xffffffffu, v, o);
    if (lane == 0) out[node] = v + b1[0];
}

// ---------------- launch ----------------
extern "C" void kernel_launch(void* const* d_in, const int* in_sizes, int n_in,
                              void* d_out, int out_size) {
    const float* x    = (const float*)d_in[0];
    const void*  ei   = d_in[1];
    const float* W0   = (const float*)d_in[2];
    const float* b0   = (const float*)d_in[3];
    const float* c11W = (const float*)d_in[4];
    const float* c11b = (const float*)d_in[5];
    const float* c12W = (const float*)d_in[6];
    const float* c12b = (const float*)d_in[7];
    const float* c21W = (const float*)d_in[8];
    const float* c21b = (const float*)d_in[9];
    const float* c22W = (const float*)d_in[10];
    const float* c22b = (const float*)d_in[11];
    const float* W1   = (const float*)d_in[12];
    const float* b1   = (const float*)d_in[13];
    float* out = (float*)d_out;

    int n = in_sizes[0] / 3;
    int e = in_sizes[1] / 2;
    if (n > NN) n = NN;
    if (e > EE) e = EE;

    const int B = 256;
    int gE  = (e + B - 1) / B;
    int gNF = (n * 32 + B - 1) / B;   // 32 thr/node
    int gP  = (n * 8 + B - 1) / B;    // 8 thr/row (prop)
    int gT  = (n + 31) / 32;          // 32-node tiles
    int nb  = (n + 1023) / 1024;
    int gSI = (n * 32 > e ? n * 32 : e);
    gSI = (gSI + B - 1) / B;

    // setup: 3 launches -> first k_prop is launch #4 (ncu capture target)
    k_count<<<gE, B>>>(ei, e);
    k_scan<<<nb, 1024>>>(n, nb);
    k_scatin<<<gSI, B>>>(ei, e, x, W0, b0, n);

    // ids: 0=h, 1=a, 2=t, 3=b
    k_prop<<<gP, B>>>(0, n);
    k_comb<<<gT, B>>>(0, -1, 1, c11W, c11b, n);
    k_prop<<<gP, B>>>(1, n);
    k_comb<<<gT, B>>>(1, 0, 3, c12W, c12b, n);
    k_prop<<<gP, B>>>(3, n);
    k_comb<<<gT, B>>>(3, -1, 1, c21W, c21b, n);
    k_prop<<<gP, B>>>(1, n);
    k_comb<<<gT, B>>>(1, 3, 0, c22W, c22b, n);

    k_final<<<gNF, B>>>(W1, b1, out, n);
}